// round 17
// baseline (speedup 1.0000x reference)
#include <cuda_runtime.h>
#include <cuda_fp16.h>
#include <cstdint>

#define NN 8192
#define FD 128
#define ALPHA 0.2f
#define PITCH 272

__device__ float  g_Wa1[FD], g_Wa2[FD];
__device__ float  g_es[NN], g_ed[NN];
__device__ unsigned g_maxu;
__device__ float  g_A[NN], g_B[NN];
__device__ float2 g_jfg[NN];
__device__ __half g_W16T[FD * FD];           // [fo][k]
__device__ __half g_WhT[(size_t)FD * NN];    // [f][node]
__device__ float  g_part[2u * NN * FD];
__device__ float  g_lsp[2 * NN];
__device__ volatile int g_bar0, g_bar1;

__device__ __forceinline__ float leakyf(float x) { return fmaxf(x, ALPHA * x); }
__device__ __forceinline__ uint32_t packh2(float x, float y) {
    __half2 h = __floats2half2_rn(x, y);
    return reinterpret_cast<uint32_t&>(h);
}
__device__ __forceinline__ void mma16816(float* c,
                                         uint32_t a0, uint32_t a1, uint32_t a2, uint32_t a3,
                                         uint32_t b0, uint32_t b1) {
    asm volatile(
        "mma.sync.aligned.m16n8k16.row.col.f32.f16.f16.f32 "
        "{%0,%1,%2,%3}, {%4,%5,%6,%7}, {%8,%9}, {%0,%1,%2,%3};\n"
        : "+f"(c[0]), "+f"(c[1]), "+f"(c[2]), "+f"(c[3])
        : "r"(a0), "r"(a1), "r"(a2), "r"(a3), "r"(b0), "r"(b1));
}
__device__ __forceinline__ void cp16(void* s, const void* g) {
    unsigned sa = (unsigned)__cvta_generic_to_shared(s);
    asm volatile("cp.async.cg.shared.global [%0], [%1], 16;\n" :: "r"(sa), "l"(g));
}
__device__ __forceinline__ void ldm4(uint32_t* r, uint32_t a) {
    asm volatile("ldmatrix.sync.aligned.m8n8.x4.shared.b16 {%0,%1,%2,%3}, [%4];"
                 : "=r"(r[0]), "=r"(r[1]), "=r"(r[2]), "=r"(r[3]) : "r"(a));
}
__device__ __forceinline__ unsigned fenc(float f) {
    unsigned b = __float_as_uint(f);
    return (b & 0x80000000u) ? ~b : (b | 0x80000000u);
}
__device__ __forceinline__ float fdec(unsigned k) {
    unsigned b = (k & 0x80000000u) ? (k & 0x7FFFFFFFu) : ~k;
    return __uint_as_float(b);
}
__device__ __forceinline__ void gridbar(volatile int* bar, int t) {
    __threadfence();
    __syncthreads();
    if (t == 0) {
        atomicAdd((int*)bar, 1);
        while (*bar < 128) { }
    }
    __syncthreads();
    __threadfence();
}

// ---- k_init: Wa1/Wa2, W fp16 transpose, reset max + barriers ----------------
__global__ void k_init(const float* __restrict__ W, const float* __restrict__ a) {
    if (blockIdx.x == 0) {
        int i = threadIdx.x;
        if (i == 0) { g_maxu = 0u; g_bar0 = 0; g_bar1 = 0; }
        if (i < FD) {
            const float* wr = W + i * FD;
            float s1 = 0.f, s2 = 0.f;
#pragma unroll 8
            for (int j = 0; j < FD; ++j) {
                float w = wr[j];
                s1 += w * a[j];
                s2 += w * a[FD + j];
            }
            g_Wa1[i] = s1; g_Wa2[i] = s2;
        }
    } else {
        int n = (blockIdx.x - 1) * 256 + threadIdx.x;
        int k = n >> 7, fo = n & 127;
        g_W16T[fo * FD + k] = __float2half(W[n]);
    }
}

// ---- k_main: esd + wh16 + pre + flash in one kernel (grid 128, all-resident)
#define OFF_P0 0
#define OFF_P1 34816
#define OFF_W0 69632
#define OFF_W1 104448
#define OFF_AB 139264
#define SMEMSZ 140288

__global__ void __launch_bounds__(512) k_main(const float* __restrict__ h,
                                              const int* __restrict__ adj) {
    extern __shared__ __align__(16) char sm[];
    const uint32_t smu = (uint32_t)__cvta_generic_to_shared(sm);
    const int t = threadIdx.x, l = t & 31, w = t >> 5;
    const int ic0 = blockIdx.x * 64;          // phase-1/2 chunk (64 rows)
    const int rg = w >> 2, nc = w & 3;

    // ================= phase 1a: es/ed (exact fp32 GEMV) =====================
    {
        float4 wa1 = *(const float4*)(g_Wa1 + l * 4);
        float4 wa2 = *(const float4*)(g_Wa2 + l * 4);
#pragma unroll
        for (int r4 = 0; r4 < 4; ++r4) {
            int i = ic0 + r4 * 16 + w;
            float4 hv = *(const float4*)(h + (size_t)i * FD + l * 4);
            float e1 = hv.x*wa1.x + hv.y*wa1.y + hv.z*wa1.z + hv.w*wa1.w;
            float e2 = hv.x*wa2.x + hv.y*wa2.y + hv.z*wa2.z + hv.w*wa2.w;
#pragma unroll
            for (int o = 16; o; o >>= 1) {
                e1 += __shfl_xor_sync(0xffffffffu, e1, o);
                e2 += __shfl_xor_sync(0xffffffffu, e2, o);
            }
            if (l == 0) {
                g_es[i] = e1; g_ed[i] = e2;
                atomicMax(&g_maxu, fenc(e2));
            }
        }
    }

    // ================= phase 1b: Wh chunk (64 x 128) fp16 HMMA ===============
    {
        char* sA = sm;                 // 64 x PITCH fp16 h rows
        char* sB = sm + 34816;         // 128 x PITCH fp16 W16T
#pragma unroll
        for (int m = 0; m < 4; ++m) {
            int idx = t + m * 512, r = idx >> 5, c4 = idx & 31;
            float4 v = *(const float4*)(h + (size_t)(ic0 + r) * FD + c4 * 4);
            uint2 pk; pk.x = packh2(v.x, v.y); pk.y = packh2(v.z, v.w);
            *(uint2*)(sA + r * PITCH + c4 * 8) = pk;
        }
#pragma unroll
        for (int m = 0; m < 4; ++m) {
            int idx = t + m * 512, r = idx >> 4, c8 = idx & 15;
            cp16(sB + r * PITCH + c8 * 16, g_W16T + r * FD + c8 * 8);
        }
        asm volatile("cp.async.commit_group;\ncp.async.wait_group 0;\n");
        __syncthreads();

        float acc[4][4];
#pragma unroll
        for (int n = 0; n < 4; ++n)
#pragma unroll
            for (int i = 0; i < 4; ++i) acc[n][i] = 0.f;
        uint32_t Ab = smu + (rg * 16 + (l & 15)) * PITCH + (l >> 4) * 16;
        uint32_t Wb = smu + 34816 + (nc * 32 + (l & 7)) * PITCH + (l >> 3) * 16;
#pragma unroll
        for (int kc2 = 0; kc2 < 4; ++kc2) {
            uint32_t a0[4], a1[4];
            ldm4(a0, Ab + kc2 * 64); ldm4(a1, Ab + kc2 * 64 + 32);
#pragma unroll
            for (int nt = 0; nt < 4; ++nt) {
                uint32_t b[4];
                ldm4(b, Wb + nt * 8 * PITCH + kc2 * 64);
                mma16816(acc[nt], a0[0], a0[1], a0[2], a0[3], b[0], b[1]);
                mma16816(acc[nt], a1[0], a1[1], a1[2], a1[3], b[2], b[3]);
            }
        }
        __syncthreads();
        float (*T)[132] = reinterpret_cast<float(*)[132]>(sm + 69632);
#pragma unroll
        for (int nt = 0; nt < 4; ++nt) {
            int row = rg * 16 + (l >> 2);
            int col = nc * 32 + nt * 8 + (l & 3) * 2;
            *(float2*)&T[row][col]     = make_float2(acc[nt][0], acc[nt][1]);
            *(float2*)&T[row + 8][col] = make_float2(acc[nt][2], acc[nt][3]);
        }
        __syncthreads();
        {
            int c = t >> 2, rseg = (t & 3) * 16;
            uint4 pk, pk2;
            pk.x  = packh2(T[rseg+0][c],  T[rseg+1][c]);
            pk.y  = packh2(T[rseg+2][c],  T[rseg+3][c]);
            pk.z  = packh2(T[rseg+4][c],  T[rseg+5][c]);
            pk.w  = packh2(T[rseg+6][c],  T[rseg+7][c]);
            pk2.x = packh2(T[rseg+8][c],  T[rseg+9][c]);
            pk2.y = packh2(T[rseg+10][c], T[rseg+11][c]);
            pk2.z = packh2(T[rseg+12][c], T[rseg+13][c]);
            pk2.w = packh2(T[rseg+14][c], T[rseg+15][c]);
            *(uint4*)(g_WhT + (size_t)c * NN + ic0 + rseg)     = pk;
            *(uint4*)(g_WhT + (size_t)c * NN + ic0 + rseg + 8) = pk2;
        }
    }

    gridbar(&g_bar0, t);   // es/ed + max + WhT global

    // ================= phase 2: A/B/jfg for chunk ============================
    if (t < 64) {
        int i = ic0 + t;
        float mx = fdec(g_maxu);
        float es = g_es[i], ed = g_ed[i];
        float m = leakyf(es + mx);
        g_A[i] = __expf(es + mx - m);
        g_B[i] = __expf(0.2f * (es + mx) - m);
        g_jfg[i] = make_float2(__expf(ed - mx), __expf(0.2f * (ed - mx)));
    }

    gridbar(&g_bar1, t);   // A/B/jfg global

    // ================= phase 3: flash (R14 body) =============================
    const int ib = blockIdx.x >> 1, jhalf = blockIdx.x & 1;
    const int i0 = ib * 128, jbase = jhalf * 4096;
    const int cg = l;
    const int rb = w * 8;
    float* sAB = (float*)(sm + OFF_AB);

    if (t < 128) { sAB[t] = g_A[i0 + t]; sAB[128 + t] = g_B[i0 + t]; }

    const uint32_t Wcol = (uint32_t)((nc * 32 + (l & 7)) * PITCH + (l >> 3) * 16);
    const uint32_t Prow = (uint32_t)((rg * 32 + (l & 15)) * PITCH + (l >> 4) * 16);
    float acc[2][4][4];
#pragma unroll
    for (int a = 0; a < 2; ++a)
#pragma unroll
        for (int n = 0; n < 4; ++n)
#pragma unroll
            for (int i = 0; i < 4; ++i) acc[a][n][i] = 0.f;
    float lsr[8];
#pragma unroll
    for (int r = 0; r < 8; ++r) lsr[r] = 0.f;

    auto issueW = [&](int buf, int jb) {
        const int j0 = jbase + jb * 128;
        char* Wt = sm + (buf ? OFF_W1 : OFF_W0);
#pragma unroll
        for (int mm = 0; mm < 4; ++mm) {
            int idx = t + mm * 512, f = idx >> 4, c8 = idx & 15;
            cp16(Wt + f * PITCH + c8 * 16, g_WhT + (size_t)f * NN + j0 + c8 * 8);
        }
    };

    issueW(0, 0);
    asm volatile("cp.async.commit_group;\n");

    int4 areg[8];
    float4 jA, jB;
    {
        const float4* jp = (const float4*)(g_jfg + jbase + cg * 4);
        jA = jp[0]; jB = jp[1];
#pragma unroll
        for (int r = 0; r < 8; ++r)
            areg[r] = *(const int4*)(adj + (size_t)(i0 + rb + r) * NN + jbase + cg * 4);
    }
    __syncthreads();

    // P(0)
    {
        char* Pp = sm + OFF_P0 + rb * PITCH + cg * 8;
#pragma unroll
        for (int r = 0; r < 8; ++r) {
            int4 q = areg[r];
            float Af = sAB[rb + r], Bf = sAB[128 + rb + r];
            float p0 = fmaxf(Af * jA.x, Bf * jA.y); p0 = q.x ? p0 : 0.f;
            float p1 = fmaxf(Af * jA.z, Bf * jA.w); p1 = q.y ? p1 : 0.f;
            float p2 = fmaxf(Af * jB.x, Bf * jB.y); p2 = q.z ? p2 : 0.f;
            float p3 = fmaxf(Af * jB.z, Bf * jB.w); p3 = q.w ? p3 : 0.f;
            lsr[r] += (p0 + p1) + (p2 + p3);
            uint2 pk; pk.x = packh2(p0, p1); pk.y = packh2(p2, p3);
            *(uint2*)(Pp + r * PITCH) = pk;
        }
        const float4* jp = (const float4*)(g_jfg + jbase + 128 + cg * 4);
        jA = jp[0]; jB = jp[1];
#pragma unroll
        for (int r = 0; r < 8; ++r)
            areg[r] = *(const int4*)(adj + (size_t)(i0 + rb + r) * NN + jbase + 128 + cg * 4);
    }

    for (int jb = 0; jb < 32; ++jb) {
        const int buf = jb & 1;
        asm volatile("cp.async.wait_group 0;\n");
        __syncthreads();
        if (jb + 1 < 32) {
            issueW(buf ^ 1, jb + 1);
            asm volatile("cp.async.commit_group;\n");
        }

        auto doP = [&]() {
            if (jb + 1 >= 32) return;
            char* Pp = sm + (buf ? OFF_P0 : OFF_P1) + rb * PITCH + cg * 8;
#pragma unroll
            for (int r = 0; r < 8; ++r) {
                int4 q = areg[r];
                float Af = sAB[rb + r], Bf = sAB[128 + rb + r];
                float p0 = fmaxf(Af * jA.x, Bf * jA.y); p0 = q.x ? p0 : 0.f;
                float p1 = fmaxf(Af * jA.z, Bf * jA.w); p1 = q.y ? p1 : 0.f;
                float p2 = fmaxf(Af * jB.x, Bf * jB.y); p2 = q.z ? p2 : 0.f;
                float p3 = fmaxf(Af * jB.z, Bf * jB.w); p3 = q.w ? p3 : 0.f;
                lsr[r] += (p0 + p1) + (p2 + p3);
                uint2 pk; pk.x = packh2(p0, p1); pk.y = packh2(p2, p3);
                *(uint2*)(Pp + r * PITCH) = pk;
            }
            if (jb + 2 < 32) {
                const int joff = jbase + (jb + 2) * 128;
                const float4* jp = (const float4*)(g_jfg + joff + cg * 4);
                jA = jp[0]; jB = jp[1];
#pragma unroll
                for (int r = 0; r < 8; ++r)
                    areg[r] = *(const int4*)(adj + (size_t)(i0 + rb + r) * NN + joff + cg * 4);
            }
        };
        auto doMMA = [&]() {
            const uint32_t Pb0 = smu + (buf ? OFF_P1 : OFF_P0) + Prow;
            const uint32_t Pb1 = Pb0 + 16 * PITCH;
            const uint32_t Wb  = smu + (buf ? OFF_W1 : OFF_W0) + Wcol;
#pragma unroll
            for (int kc2 = 0; kc2 < 4; ++kc2) {
                uint32_t a0[4], a1[4], a2[4], a3[4];
                ldm4(a0, Pb0 + kc2 * 64); ldm4(a1, Pb0 + kc2 * 64 + 32);
                ldm4(a2, Pb1 + kc2 * 64); ldm4(a3, Pb1 + kc2 * 64 + 32);
#pragma unroll
                for (int nt = 0; nt < 4; ++nt) {
                    uint32_t b[4];
                    ldm4(b, Wb + nt * 8 * PITCH + kc2 * 64);
                    mma16816(acc[0][nt], a0[0], a0[1], a0[2], a0[3], b[0], b[1]);
                    mma16816(acc[0][nt], a1[0], a1[1], a1[2], a1[3], b[2], b[3]);
                    mma16816(acc[1][nt], a2[0], a2[1], a2[2], a2[3], b[0], b[1]);
                    mma16816(acc[1][nt], a3[0], a3[1], a3[2], a3[3], b[2], b[3]);
                }
            }
        };

        if (w & 1) { doMMA(); doP(); }
        else       { doP(); doMMA(); }
    }

    // row sums
#pragma unroll
    for (int r = 0; r < 8; ++r) {
        float v = lsr[r];
#pragma unroll
        for (int o = 16; o; o >>= 1) v += __shfl_xor_sync(0xffffffffu, v, o);
        if (l == r) g_lsp[jhalf * NN + i0 + rb + r] = v;
    }
    // partial numerator
#pragma unroll
    for (int a = 0; a < 2; ++a)
#pragma unroll
        for (int nt = 0; nt < 4; ++nt) {
            int row = i0 + rg * 32 + a * 16 + (l >> 2);
            int col = nc * 32 + nt * 8 + (l & 3) * 2;
            *(float2*)&g_part[((size_t)jhalf * NN + row) * FD + col] =
                make_float2(acc[a][nt][0], acc[a][nt][1]);
            *(float2*)&g_part[((size_t)jhalf * NN + row + 8) * FD + col] =
                make_float2(acc[a][nt][2], acc[a][nt][3]);
        }
}

// ---- k_comb -----------------------------------------------------------------
__global__ void k_comb(float* __restrict__ out) {
    int idx = blockIdx.x * 512 + threadIdx.x;
    int i = idx >> 7;
    float num = g_part[idx] + g_part[(size_t)NN * FD + idx];
    float den = g_lsp[i] + g_lsp[NN + i];
    out[idx] = num / den;
}

// ---- launcher ---------------------------------------------------------------
extern "C" void kernel_launch(void* const* d_in, const int* in_sizes, int n_in,
                              void* d_out, int out_size) {
    const float* h   = (const float*)d_in[0];
    const int*   adj = (const int*)d_in[1];
    const float* W   = (const float*)d_in[2];
    const float* a   = (const float*)d_in[3];
    float* out = (float*)d_out;

    k_init<<<65, 256>>>(W, a);
    cudaFuncSetAttribute(k_main, cudaFuncAttributeMaxDynamicSharedMemorySize, SMEMSZ);
    k_main<<<128, 512, SMEMSZ>>>(h, adj);
    k_comb<<<NN * FD / 512, 512>>>(out);
}